// round 16
// baseline (speedup 1.0000x reference)
#include <cuda_runtime.h>
#include <cuda_fp16.h>
#include <cstdint>

#define NROWS 8192
#define IN_F  4096
#define OUT_F 4096
#define RANK  1024

#define BM 128
#define BN 256
#define BK 64                          // fp16 K-elems per stage
#define STRB 144                       // 128B payload + 16 pad
#define A_TILE (128 * STRB)            // 18432
#define STG_B  A_TILE                  // stage = A only; B goes direct from L2
#define STAGES 3
#define SMEM_TOTAL (STAGES * STG_B)    // 55296
#define NTHR 512

#define CV_TASKS 128
#define G1_TASKS 256
#define G2_TASKS 1024
#define G1_BASE  CV_TASKS
#define G2_BASE  (CV_TASKS + G1_TASKS)
#define NTASKS   (CV_TASKS + G1_TASKS + G2_TASKS)
#define PERSIST  152

// ---------------- scratch ----------------
__device__ __half g_h [(size_t)NROWS * RANK];
__device__ __half g_vh[(size_t)RANK  * IN_F];
__device__ __half g_u [(size_t)OUT_F * RANK];
__device__ unsigned g_ticket;
__device__ unsigned g_fvh[4];
__device__ unsigned g_fu[16];
__device__ unsigned g_fh[64];

__global__ void k_reset() {
    int r = threadIdx.x;
    if (r == 0) g_ticket = 0;
    if (r < 4)  g_fvh[r] = 0;
    if (r < 16) g_fu[r]  = 0;
    if (r < 64) g_fh[r]  = 0;
}

// ---------------- PTX helpers ----------------
__device__ __forceinline__ void cp16(uint32_t dst, const void* src) {
    asm volatile("cp.async.cg.shared.global [%0], [%1], 16;" :: "r"(dst), "l"(src) : "memory");
}
#define CP_COMMIT() asm volatile("cp.async.commit_group;" ::: "memory")
#define CP_WAIT1()  asm volatile("cp.async.wait_group 1;" ::: "memory")
#define CP_WAIT0()  asm volatile("cp.async.wait_group 0;" ::: "memory")
__device__ __forceinline__ uint32_t smem_u32(const void* p) {
    uint32_t a;
    asm("{ .reg .u64 t; cvta.to.shared.u64 t, %1; cvt.u32.u64 %0, t; }" : "=r"(a) : "l"(p));
    return a;
}
__device__ __forceinline__ void hmma(float* d, const uint32_t* a, uint32_t b0, uint32_t b1) {
    asm volatile(
        "mma.sync.aligned.m16n8k16.row.col.f32.f16.f16.f32 "
        "{%0,%1,%2,%3}, {%4,%5,%6,%7}, {%8,%9}, {%0,%1,%2,%3};\n"
        : "+f"(d[0]), "+f"(d[1]), "+f"(d[2]), "+f"(d[3])
        : "r"(a[0]), "r"(a[1]), "r"(a[2]), "r"(a[3]), "r"(b0), "r"(b1));
}
__device__ __forceinline__ void ldsm4(uint32_t* f, uint32_t addr) {
    asm volatile("ldmatrix.sync.aligned.m8n8.x4.shared.b16 {%0,%1,%2,%3}, [%4];"
                 : "=r"(f[0]), "=r"(f[1]), "=r"(f[2]), "=r"(f[3]) : "r"(addr));
}
__device__ __forceinline__ void sts16(uint32_t addr, uint32_t x, uint32_t y, uint32_t z, uint32_t w) {
    asm volatile("st.shared.v4.b32 [%0], {%1,%2,%3,%4};" :: "r"(addr), "r"(x), "r"(y), "r"(z), "r"(w));
}
__device__ __forceinline__ uint32_t h2u(__half2 h) {
    union { __half2 h; uint32_t u; } c; c.h = h; return c.u;
}
__device__ __forceinline__ unsigned ld_acq(const unsigned* p) {
    unsigned v;
    asm volatile("ld.acquire.gpu.global.u32 %0, [%1];" : "=r"(v) : "l"(p) : "memory");
    return v;
}

// ---------------- weight-convert task ----------------
__device__ __forceinline__ void convert_chunk(const int* __restrict__ src, __half* __restrict__ dst,
                                              int vec_base, int nvec, int tid) {
    for (int i = tid; i < nvec; i += NTHR) {
        const int j = vec_base + i;
        int4 v = ((const int4*)src)[j];
        *(__half2*)(dst + (size_t)j * 4)     = __halves2half2(__int2half_rn(v.x - 128), __int2half_rn(v.y - 128));
        *(__half2*)(dst + (size_t)j * 4 + 2) = __halves2half2(__int2half_rn(v.z - 128), __int2half_rn(v.w - 128));
    }
}

// ---------------- one GEMM tile task ----------------
// 16 warps, warp tile 64x32. A: smem 3-stage. B: direct LDG from L2 in mma
// fragment layout (lane L: col=n0+L/4, k=k0+(L%4)*2; b1 at +8), 1-slice lookahead.
template<int MODE>
__device__ __forceinline__ void run_tile(uint32_t sb, int bm, int bn,
                                         const float* __restrict__ xf,
                                         float us, float csv, float csz,
                                         const int* __restrict__ Sd,
                                         const float* __restrict__ bias,
                                         float* __restrict__ out) {
    constexpr int K = (MODE == 0) ? IN_F : RANK;
    constexpr int T = K / BK;
    constexpr int NSLICE = K / 16;

    const int tid  = threadIdx.x;
    const int lane = tid & 31;
    const int wid  = tid >> 5;
    const int wm   = wid & 1;          // 2 warp-rows (64 M)
    const int wn   = wid >> 1;         // 8 warp-cols (32 N)

    const __half* Bw = (MODE == 0) ? g_vh : g_u;

    float acc[4][4][4];
#pragma unroll
    for (int a = 0; a < 4; ++a)
#pragma unroll
        for (int b = 0; b < 4; ++b)
#pragma unroll
            for (int c = 0; c < 4; ++c) acc[a][b][c] = 0.f;

    // ---- A producers (smem stages) ----
    const int r0 = tid >> 2;           // 0..127 row
    const int c0 = tid & 3;            // 32B chunk col
    // MODE 0: fp32 x -> regs -> fp16 smem ; 2 chunks/thread (cols 0..7 of 128B row)
    float4 ar[4];
    auto ldA = [&](int t) {
        const int k0 = t * BK;
        const float* p = xf + (size_t)(bm + r0) * IN_F + k0 + c0 * 16;
        ar[0] = *(const float4*)p;
        ar[1] = *(const float4*)(p + 4);
        ar[2] = *(const float4*)(p + 8);
        ar[3] = *(const float4*)(p + 12);
    };
    auto stA = [&](int t) {
        const uint32_t da = sb + (t % STAGES) * STG_B + r0 * STRB + c0 * 32;
        const uint32_t u0 = h2u(__floats2half2_rn(ar[0].x, ar[0].y));
        const uint32_t u1 = h2u(__floats2half2_rn(ar[0].z, ar[0].w));
        const uint32_t u2 = h2u(__floats2half2_rn(ar[1].x, ar[1].y));
        const uint32_t u3 = h2u(__floats2half2_rn(ar[1].z, ar[1].w));
        sts16(da, u0, u1, u2, u3);
        const uint32_t u4 = h2u(__floats2half2_rn(ar[2].x, ar[2].y));
        const uint32_t u5 = h2u(__floats2half2_rn(ar[2].z, ar[2].w));
        const uint32_t u6 = h2u(__floats2half2_rn(ar[3].x, ar[3].y));
        const uint32_t u7 = h2u(__floats2half2_rn(ar[3].z, ar[3].w));
        sts16(da + 16, u4, u5, u6, u7);
    };
    // MODE 1: fp16 h via cp.async ; 1 chunk of 32B/thread
    auto issueA1 = [&](int t) {
        const uint32_t stg = sb + (t % STAGES) * STG_B;
        const int k0 = t * BK;
        const uint32_t da = stg + r0 * STRB + c0 * 32;
        const __half* p = g_h + (size_t)(bm + r0) * K + k0 + c0 * 16;
        cp16(da, p);
        cp16(da + 16, p + 8);
    };

    // ---- B direct-LDG fragment loader ----
    const __half* bp0 = Bw + (size_t)(bn + wn * 32 + (lane >> 2)) * K + ((lane & 3) << 1);
    uint32_t fb[2][8];                 // [slice parity][nt*2 + {b0,b1}]
    auto ldB = [&](int s) {
        const __half* p = bp0 + s * 16;
        uint32_t* dst = fb[s & 1];
#pragma unroll
        for (int nt = 0; nt < 4; ++nt) {
            dst[2 * nt]     = *(const uint32_t*)(p + (size_t)nt * 8 * K);
            dst[2 * nt + 1] = *(const uint32_t*)(p + (size_t)nt * 8 * K + 8);
        }
    };

    // ---- prologue ----
    if (MODE == 0) { ldA(0); stA(0); ldA(1); stA(1); }
    else {
        issueA1(0); CP_COMMIT();
        issueA1(1); CP_COMMIT();
    }
    ldB(0);                            // first B slice

    const int grp = lane >> 3, win = lane & 7;
    const uint32_t aoff = (wm * 64 + ((grp & 1) << 3) + win) * STRB + ((grp >> 1) << 4);

    uint32_t fa[2][4];

    for (int t = 0; t < T; ++t) {
        if (MODE == 1) CP_WAIT1();
        __syncthreads();
        if (t + 2 < T) {
            if (MODE == 0) ldA(t + 2);
            else { issueA1(t + 2); CP_COMMIT(); }
        } else if (MODE == 1) CP_COMMIT();

        const uint32_t ab = sb + (t % STAGES) * STG_B + aoff;
        ldsm4(fa[0], ab);              // prime A ks=0 mt=0
#pragma unroll
        for (int ks = 0; ks < 4; ++ks) {
            const uint32_t co = ks * 32;
            const int s = t * 4 + ks;
            if (s + 1 < NSLICE) ldB(s + 1);   // B lookahead crosses iters freely
#pragma unroll
            for (int mt = 0; mt < 4; ++mt) {
                if (mt < 3)      ldsm4(fa[(mt + 1) & 1], ab + (mt + 1) * 16 * STRB + co);
                else if (ks < 3) ldsm4(fa[0],            ab + co + 32);
                const uint32_t* a = fa[mt & 1];
                const uint32_t* b = fb[s & 1];
#pragma unroll
                for (int nt = 0; nt < 4; ++nt)
                    hmma(acc[mt][nt], a, b[2 * nt], b[2 * nt + 1]);
            }
        }
        if (MODE == 0 && t + 2 < T) stA(t + 2);
    }
    if (MODE == 1) CP_WAIT0();

    // ---- epilogue ----
    const int fr = lane >> 2;
    const int fq = (lane & 3) * 2;
#pragma unroll
    for (int mt = 0; mt < 4; ++mt) {
#pragma unroll
        for (int nt = 0; nt < 4; ++nt) {
            const int row0 = bm + wm * 64 + mt * 16 + fr;
            const int col0 = bn + wn * 32 + nt * 8 + fq;
#pragma unroll
            for (int h = 0; h < 2; ++h) {
                const int row = row0 + h * 8;
                const float v0 = acc[mt][nt][2 * h + 0];
                const float v1 = acc[mt][nt][2 * h + 1];
                if (MODE == 0) {
                    const float s0 = csv * ((float)Sd[col0]     - csz);
                    const float s1 = csv * ((float)Sd[col0 + 1] - csz);
                    *(__half2*)(g_h + (size_t)row * RANK + col0) =
                        __halves2half2(__float2half_rn(v0 * s0), __float2half_rn(v1 * s1));
                } else {
                    float2 y;
                    y.x = v0 * us + bias[col0];
                    y.y = v1 * us + bias[col0 + 1];
                    *(float2*)(out + (size_t)row * OUT_F + col0) = y;
                }
            }
        }
    }
}

// ---------------- persistent fused kernel ----------------
__global__ void __launch_bounds__(NTHR, 1)
gemm_persistent(const float* __restrict__ xf,
                const int* __restrict__ Vhd, const int* __restrict__ Ud,
                const int* __restrict__ Sd,
                const float* __restrict__ Usp, const float* __restrict__ vhs,
                const float* __restrict__ ss, const float* __restrict__ szp,
                const float* __restrict__ bias, float* __restrict__ out) {
    extern __shared__ char smem[];
    __shared__ unsigned s_task;
    const uint32_t sb = smem_u32(smem);
    const int tid = threadIdx.x;

    for (;;) {
        if (tid == 0) s_task = atomicAdd(&g_ticket, 1u);
        __syncthreads();
        const unsigned task = s_task;
        if (task >= NTASKS) break;

        if (task < CV_TASKS) {
            if (task < 64) {
                convert_chunk(Vhd, g_vh, (int)task * 16384, 16384, tid);
                __syncthreads();
                if (tid == 0) { __threadfence(); atomicAdd(&g_fvh[task >> 4], 1u); }
            } else {
                const unsigned u = task - 64;
                convert_chunk(Ud, g_u, (int)u * 16384, 16384, tid);
                __syncthreads();
                if (tid == 0) { __threadfence(); atomicAdd(&g_fu[u >> 2], 1u); }
            }
        } else if (task < G2_BASE) {
            const unsigned g = task - G1_BASE;
            const int m = g >> 2, n = g & 3;
            if (tid == 0) {
                while (ld_acq(&g_fvh[n]) < 16) __nanosleep(128);
            }
            __syncthreads();
            const float csv = vhs[0] * ss[0];
            const float csz = szp[0];
            run_tile<0>(sb, m * BM, n * BN, xf, 0.f, csv, csz, Sd, bias, out);
            __syncthreads();
            if (tid == 0) { __threadfence(); atomicAdd(&g_fh[m], 1u); }
        } else {
            const unsigned g = task - G2_BASE;
            const int m = g >> 4, n = g & 15;
            if (tid == 0) {
                while (ld_acq(&g_fu[n]) < 4) __nanosleep(128);
                while (ld_acq(&g_fh[m]) < 4) __nanosleep(128);
            }
            __syncthreads();
            run_tile<1>(sb, m * BM, n * BN, xf, Usp[0], 0.f, 0.f, Sd, bias, out);
        }
        __syncthreads();
    }
}

// ---------------- launch ----------------
extern "C" void kernel_launch(void* const* d_in, const int* in_sizes, int n_in,
                              void* d_out, int out_size) {
    const float* x    = (const float*)d_in[0];
    const int*   Ud   = (const int*)  d_in[1];
    const float* Us   = (const float*)d_in[2];
    const int*   Sd   = (const int*)  d_in[4];
    const float* Ss   = (const float*)d_in[5];
    const float* Szp  = (const float*)d_in[6];
    const int*   Vhd  = (const int*)  d_in[7];
    const float* Vhs  = (const float*)d_in[8];
    const float* bias = (const float*)d_in[10];
    float* out = (float*)d_out;
    (void)in_sizes; (void)n_in; (void)out_size;

    cudaFuncSetAttribute(gemm_persistent, cudaFuncAttributeMaxDynamicSharedMemorySize, SMEM_TOTAL);

    k_reset<<<1, 64>>>();
    gemm_persistent<<<PERSIST, NTHR, SMEM_TOTAL>>>(x, Vhd, Ud, Sd, Us, Vhs, Ss, Szp, bias, out);
}

// round 17
// speedup vs baseline: 1.7880x; 1.7880x over previous
#include <cuda_runtime.h>
#include <cuda_fp16.h>
#include <cstdint>

#define NROWS 8192
#define IN_F  4096
#define OUT_F 4096
#define RANK  1024

#define BM 128
#define BN 256
#define BK 64                          // fp16 K-elems per stage (128B rows)
#define STRB 144                       // 128 payload + 16 pad
#define A_TILE (128 * STRB)            // 18432
#define B_TILE (256 * STRB)            // 36864
#define STG_B  (A_TILE + B_TILE)       // 55296
#define STAGES 3
#define SMEM_TOTAL (STAGES * STG_B)    // 165888
#define NTHR 256                       // 8 warps, warp tile 64x64

#define CV_TASKS 128
#define G1_TASKS 256
#define G2_TASKS 1024
#define G1_BASE  CV_TASKS
#define G2_BASE  (CV_TASKS + G1_TASKS)
#define NTASKS   (CV_TASKS + G1_TASKS + G2_TASKS)
#define PERSIST  152

// ---------------- scratch ----------------
__device__ __half g_h [(size_t)NROWS * RANK];
__device__ __half g_vh[(size_t)RANK  * IN_F];
__device__ __half g_u [(size_t)OUT_F * RANK];
__device__ unsigned g_ticket;
__device__ unsigned g_fvh[4];
__device__ unsigned g_fu[16];
__device__ unsigned g_fh[64];

__global__ void k_reset() {
    int r = threadIdx.x;
    if (r == 0) g_ticket = 0;
    if (r < 4)  g_fvh[r] = 0;
    if (r < 16) g_fu[r]  = 0;
    if (r < 64) g_fh[r]  = 0;
}

// ---------------- PTX helpers ----------------
__device__ __forceinline__ void cp16(uint32_t dst, const void* src) {
    asm volatile("cp.async.cg.shared.global [%0], [%1], 16;" :: "r"(dst), "l"(src) : "memory");
}
#define CP_COMMIT() asm volatile("cp.async.commit_group;" ::: "memory")
#define CP_WAIT1()  asm volatile("cp.async.wait_group 1;" ::: "memory")
#define CP_WAIT0()  asm volatile("cp.async.wait_group 0;" ::: "memory")
__device__ __forceinline__ uint32_t smem_u32(const void* p) {
    uint32_t a;
    asm("{ .reg .u64 t; cvta.to.shared.u64 t, %1; cvt.u32.u64 %0, t; }" : "=r"(a) : "l"(p));
    return a;
}
__device__ __forceinline__ void hmma(float* d, const uint32_t* a, uint32_t b0, uint32_t b1) {
    asm volatile(
        "mma.sync.aligned.m16n8k16.row.col.f32.f16.f16.f32 "
        "{%0,%1,%2,%3}, {%4,%5,%6,%7}, {%8,%9}, {%0,%1,%2,%3};\n"
        : "+f"(d[0]), "+f"(d[1]), "+f"(d[2]), "+f"(d[3])
        : "r"(a[0]), "r"(a[1]), "r"(a[2]), "r"(a[3]), "r"(b0), "r"(b1));
}
__device__ __forceinline__ void ldsm4(uint32_t* f, uint32_t addr) {
    asm volatile("ldmatrix.sync.aligned.m8n8.x4.shared.b16 {%0,%1,%2,%3}, [%4];"
                 : "=r"(f[0]), "=r"(f[1]), "=r"(f[2]), "=r"(f[3]) : "r"(addr));
}
__device__ __forceinline__ void sts16(uint32_t addr, uint32_t x, uint32_t y, uint32_t z, uint32_t w) {
    asm volatile("st.shared.v4.b32 [%0], {%1,%2,%3,%4};" :: "r"(addr), "r"(x), "r"(y), "r"(z), "r"(w));
}
__device__ __forceinline__ uint32_t h2u(__half2 h) {
    union { __half2 h; uint32_t u; } c; c.h = h; return c.u;
}
__device__ __forceinline__ unsigned ld_acq(const unsigned* p) {
    unsigned v;
    asm volatile("ld.acquire.gpu.global.u32 %0, [%1];" : "=r"(v) : "l"(p) : "memory");
    return v;
}

// ---------------- weight-convert task ----------------
__device__ __forceinline__ void convert_chunk(const int* __restrict__ src, __half* __restrict__ dst,
                                              int vec_base, int nvec, int tid) {
    for (int i = tid; i < nvec; i += NTHR) {
        const int j = vec_base + i;
        int4 v = ((const int4*)src)[j];
        *(__half2*)(dst + (size_t)j * 4)     = __halves2half2(__int2half_rn(v.x - 128), __int2half_rn(v.y - 128));
        *(__half2*)(dst + (size_t)j * 4 + 2) = __halves2half2(__int2half_rn(v.z - 128), __int2half_rn(v.w - 128));
    }
}

// ---------------- one GEMM tile task ----------------
// 8 warps, warp tile 64x64, BK=64, register fragment pipeline (A and B).
template<int MODE>
__device__ __forceinline__ void run_tile(uint32_t sb, int bm, int bn,
                                         const float* __restrict__ xf,
                                         float us, float csv, float csz,
                                         const int* __restrict__ Sd,
                                         const float* __restrict__ bias,
                                         float* __restrict__ out) {
    constexpr int K = (MODE == 0) ? IN_F : RANK;
    constexpr int T = K / BK;

    const int tid  = threadIdx.x;
    const int lane = tid & 31;
    const int wid  = tid >> 5;
    const int wm   = wid & 1;          // 2 warp-rows (64 M each)
    const int wn   = wid >> 1;         // 4 warp-cols (64 N each)

    const __half* Bw = (MODE == 0) ? g_vh : g_u;

    float acc[4][8][4];
#pragma unroll
    for (int a = 0; a < 4; ++a)
#pragma unroll
        for (int b = 0; b < 8; ++b)
#pragma unroll
            for (int c = 0; c < 4; ++c) acc[a][b][c] = 0.f;

    // ---- producers (256 threads, 16B chunks): A 1024 chunks (4/thr), B 2048 (8/thr)
    auto issueB = [&](int t) {
        const uint32_t stg = sb + (t % STAGES) * STG_B;
        const int k0 = t * BK;
#pragma unroll
        for (int q = 0; q < 8; ++q) {
            const int ch = tid + NTHR * q;
            const int row = ch >> 3, col = ch & 7;
            cp16(stg + A_TILE + row * STRB + col * 16,
                 Bw + (size_t)(bn + row) * K + k0 + col * 8);
        }
    };
    float4 ar[8];
    auto ldA = [&](int t) {
        const int k0 = t * BK;
#pragma unroll
        for (int q = 0; q < 4; ++q) {
            const int ch = tid + NTHR * q;
            const int row = ch >> 3, col = ch & 7;
            const float* p = xf + (size_t)(bm + row) * IN_F + k0 + col * 8;
            ar[2 * q]     = *(const float4*)p;
            ar[2 * q + 1] = *(const float4*)(p + 4);
        }
    };
    auto stA = [&](int t) {
        const uint32_t stg = sb + (t % STAGES) * STG_B;
#pragma unroll
        for (int q = 0; q < 4; ++q) {
            const int ch = tid + NTHR * q;
            const int row = ch >> 3, col = ch & 7;
            const uint32_t u0 = h2u(__floats2half2_rn(ar[2*q].x,   ar[2*q].y));
            const uint32_t u1 = h2u(__floats2half2_rn(ar[2*q].z,   ar[2*q].w));
            const uint32_t u2 = h2u(__floats2half2_rn(ar[2*q+1].x, ar[2*q+1].y));
            const uint32_t u3 = h2u(__floats2half2_rn(ar[2*q+1].z, ar[2*q+1].w));
            sts16(stg + row * STRB + col * 16, u0, u1, u2, u3);
        }
    };
    auto issueA1 = [&](int t) {
        const uint32_t stg = sb + (t % STAGES) * STG_B;
        const int k0 = t * BK;
#pragma unroll
        for (int q = 0; q < 4; ++q) {
            const int ch = tid + NTHR * q;
            const int row = ch >> 3, col = ch & 7;
            cp16(stg + row * STRB + col * 16,
                 g_h + (size_t)(bm + row) * K + k0 + col * 8);
        }
    };

    if (MODE == 0) { ldA(0); stA(0); ldA(1); stA(1); }
    else           { issueA1(0); }
    issueB(0); CP_COMMIT();
    if (MODE == 1) issueA1(1);
    issueB(1); CP_COMMIT();

    const int grp = lane >> 3, win = lane & 7;
    const uint32_t aoff = (wm * 64 + ((grp & 1) << 3) + win) * STRB + ((grp >> 1) << 4);
    const uint32_t boff = A_TILE + (wn * 64 + ((grp >> 1) << 3) + win) * STRB + ((grp & 1) << 4);

    uint32_t fb[2][16];   // B frags: 8 nt x 2 regs, double-buffered per k16 slice
    uint32_t fa[2][4];    // A frags: one mt, double-buffered

    for (int t = 0; t < T; ++t) {
        CP_WAIT1();
        __syncthreads();
        if (t + 2 < T) {
            if (MODE == 0) ldA(t + 2); else issueA1(t + 2);
            issueB(t + 2);
        }
        CP_COMMIT();

        const uint32_t ab = sb + (t % STAGES) * STG_B + aoff;
        const uint32_t bb = sb + (t % STAGES) * STG_B + boff;

        // prime ks=0
#pragma unroll
        for (int ntp = 0; ntp < 4; ++ntp)
            ldsm4(&fb[0][4 * ntp], bb + ntp * 16 * STRB);
        ldsm4(fa[0], ab);
#pragma unroll
        for (int ks = 0; ks < 4; ++ks) {
            const uint32_t co = ks * 32;
            if (ks < 3) {        // B for ks+1, consumed 32 HMMAs later
#pragma unroll
                for (int ntp = 0; ntp < 4; ++ntp)
                    ldsm4(&fb[(ks + 1) & 1][4 * ntp], bb + ntp * 16 * STRB + co + 32);
            }
#pragma unroll
            for (int mt = 0; mt < 4; ++mt) {
                if (mt < 3)      ldsm4(fa[(mt + 1) & 1], ab + (mt + 1) * 16 * STRB + co);
                else if (ks < 3) ldsm4(fa[0],            ab + co + 32);
                const uint32_t* a = fa[mt & 1];
                const uint32_t* b = fb[ks & 1];
#pragma unroll
                for (int nt = 0; nt < 8; ++nt)
                    hmma(acc[mt][nt], a, b[2 * nt], b[2 * nt + 1]);
            }
        }
        if (MODE == 0 && t + 2 < T) stA(t + 2);
    }
    CP_WAIT0();

    // ---- epilogue ----
    const int fr = lane >> 2;
    const int fq = (lane & 3) * 2;
#pragma unroll
    for (int mt = 0; mt < 4; ++mt) {
#pragma unroll
        for (int nt = 0; nt < 8; ++nt) {
            const int row0 = bm + wm * 64 + mt * 16 + fr;
            const int col0 = bn + wn * 64 + nt * 8 + fq;
#pragma unroll
            for (int h = 0; h < 2; ++h) {
                const int row = row0 + h * 8;
                const float v0 = acc[mt][nt][2 * h + 0];
                const float v1 = acc[mt][nt][2 * h + 1];
                if (MODE == 0) {
                    const float s0 = csv * ((float)Sd[col0]     - csz);
                    const float s1 = csv * ((float)Sd[col0 + 1] - csz);
                    *(__half2*)(g_h + (size_t)row * RANK + col0) =
                        __halves2half2(__float2half_rn(v0 * s0), __float2half_rn(v1 * s1));
                } else {
                    float2 y;
                    y.x = v0 * us + bias[col0];
                    y.y = v1 * us + bias[col0 + 1];
                    *(float2*)(out + (size_t)row * OUT_F + col0) = y;
                }
            }
        }
    }
}

// ---------------- persistent fused kernel ----------------
__global__ void __launch_bounds__(NTHR, 1)
gemm_persistent(const float* __restrict__ xf,
                const int* __restrict__ Vhd, const int* __restrict__ Ud,
                const int* __restrict__ Sd,
                const float* __restrict__ Usp, const float* __restrict__ vhs,
                const float* __restrict__ ss, const float* __restrict__ szp,
                const float* __restrict__ bias, float* __restrict__ out) {
    extern __shared__ char smem[];
    __shared__ unsigned s_task;
    const uint32_t sb = smem_u32(smem);
    const int tid = threadIdx.x;

    for (;;) {
        if (tid == 0) s_task = atomicAdd(&g_ticket, 1u);
        __syncthreads();
        const unsigned task = s_task;
        if (task >= NTASKS) break;

        if (task < CV_TASKS) {
            if (task < 64) {
                convert_chunk(Vhd, g_vh, (int)task * 16384, 16384, tid);
                __syncthreads();
                if (tid == 0) { __threadfence(); atomicAdd(&g_fvh[task >> 4], 1u); }
            } else {
                const unsigned u = task - 64;
                convert_chunk(Ud, g_u, (int)u * 16384, 16384, tid);
                __syncthreads();
                if (tid == 0) { __threadfence(); atomicAdd(&g_fu[u >> 2], 1u); }
            }
        } else if (task < G2_BASE) {
            const unsigned g = task - G1_BASE;
            const int m = g >> 2, n = g & 3;
            if (tid == 0) {
                while (ld_acq(&g_fvh[n]) < 16) __nanosleep(128);
            }
            __syncthreads();
            const float csv = vhs[0] * ss[0];
            const float csz = szp[0];
            run_tile<0>(sb, m * BM, n * BN, xf, 0.f, csv, csz, Sd, bias, out);
            __syncthreads();
            if (tid == 0) { __threadfence(); atomicAdd(&g_fh[m], 1u); }
        } else {
            const unsigned g = task - G2_BASE;
            const int m = g >> 4, n = g & 15;
            if (tid == 0) {
                while (ld_acq(&g_fu[n]) < 4) __nanosleep(128);
                while (ld_acq(&g_fh[m]) < 4) __nanosleep(128);
            }
            __syncthreads();
            run_tile<1>(sb, m * BM, n * BN, xf, Usp[0], 0.f, 0.f, Sd, bias, out);
        }
        __syncthreads();
    }
}

// ---------------- launch ----------------
extern "C" void kernel_launch(void* const* d_in, const int* in_sizes, int n_in,
                              void* d_out, int out_size) {
    const float* x    = (const float*)d_in[0];
    const int*   Ud   = (const int*)  d_in[1];
    const float* Us   = (const float*)d_in[2];
    const int*   Sd   = (const int*)  d_in[4];
    const float* Ss   = (const float*)d_in[5];
    const float* Szp  = (const float*)d_in[6];
    const int*   Vhd  = (const int*)  d_in[7];
    const float* Vhs  = (const float*)d_in[8];
    const float* bias = (const float*)d_in[10];
    float* out = (float*)d_out;
    (void)in_sizes; (void)n_in; (void)out_size;

    cudaFuncSetAttribute(gemm_persistent, cudaFuncAttributeMaxDynamicSharedMemorySize, SMEM_TOTAL);

    k_reset<<<1, 64>>>();
    gemm_persistent<<<PERSIST, NTHR, SMEM_TOTAL>>>(x, Vhd, Ud, Sd, Us, Vhs, Ss, Szp, bias, out);
}